// round 2
// baseline (speedup 1.0000x reference)
#include <cuda_runtime.h>

// ---------------- scratch (device globals; no runtime allocation) ----------------
__device__ float g_enc_b1[16 * 128 * 128 * 128]; // [16,128,128,128]
__device__ float g_enc_b [16 * 128 * 64 * 64];   // [16,128,64,64]
__device__ float g_enc_t [16 * 128 * 32 * 32];   // [16,128,32,32]
__device__ float g_zt    [16384 * 64];           // [B*32*32, 64]
__device__ float g_zb    [65536 * 64];           // [B*64*64, 64]
__device__ float g_dec_t [16 * 64 * 64 * 64];    // [16,64,64,64]
__device__ float g_up_t  [16 * 64 * 64 * 64];    // [16,64,64,64]
__device__ float g_h     [16 * 64 * 128 * 128];  // [16,64,128,128]
__device__ int   g_idx_t [16384];
__device__ int   g_idx_b [65536];
__device__ float g_norm_t[512];
__device__ float g_norm_b[512];
__device__ float g_dsum[2];

// ---------------- init ----------------
__global__ void zero_sums_kernel() {
    g_dsum[0] = 0.f;
    g_dsum[1] = 0.f;
}

// ---------------- embed norms: ||e_k||^2, embed layout [64, K] ----------------
__global__ void embed_norms_kernel(const float* __restrict__ e, float* __restrict__ out, int K) {
    int k = blockIdx.x * blockDim.x + threadIdx.x;
    if (k >= K) return;
    float s = 0.f;
    for (int d = 0; d < 64; d++) {
        float v = e[d * K + k];
        s += v * v;
    }
    out[k] = s;
}

// ---------------- conv k4 s2 p1 (+bias, optional relu) ----------------
// output tile 8(H) x 16(W), COUT tile 32; 256 threads: cg=tid>>6 (8 couts each),
// sp=tid&63 -> 2 spatial positions (oy0, oy0+4). CI chunk = 8 with zero-pad guards.
__global__ __launch_bounds__(256)
void conv_s2k4_kernel(const float* __restrict__ in, const float* __restrict__ w,
                      const float* __restrict__ bias, float* __restrict__ out,
                      int N, int Cin, int Cout, int Hi, int Wi, int Ho, int Wo, int relu)
{
    __shared__ float s_in[8][18][34];
    __shared__ float s_w[32][8][16];

    int tid = threadIdx.x;
    int cg  = tid >> 6;   // 0..3
    int sp  = tid & 63;
    int oy0 = sp >> 4;    // 0..3
    int ox  = sp & 15;

    int nCo = Cout >> 5;
    int n   = blockIdx.z / nCo;
    int co0 = (blockIdx.z % nCo) << 5;
    int oh0 = blockIdx.y * 8;
    int ow0 = blockIdx.x * 16;
    int ih0 = 2 * oh0 - 1;
    int iw0 = 2 * ow0 - 1;

    float acc0[8], acc1[8];
#pragma unroll
    for (int u = 0; u < 8; u++) { acc0[u] = 0.f; acc1[u] = 0.f; }

    for (int ci0 = 0; ci0 < Cin; ci0 += 8) {
        // load input tile (zero padded)
        for (int e = tid; e < 8 * 18 * 34; e += 256) {
            int ci = e / (18 * 34);
            int r  = (e / 34) % 18;
            int c  = e % 34;
            int gci = ci0 + ci;
            int gr = ih0 + r, gc = iw0 + c;
            float v = 0.f;
            if (gci < Cin && gr >= 0 && gr < Hi && gc >= 0 && gc < Wi)
                v = in[((n * Cin + gci) * Hi + gr) * Wi + gc];
            s_in[ci][r][c] = v;
        }
        // load weights [co][ci][tap]
        for (int e = tid; e < 32 * 8 * 16; e += 256) {
            int co  = e >> 7;
            int ci  = (e >> 4) & 7;
            int tap = e & 15;
            int gci = ci0 + ci;
            float v = 0.f;
            if (gci < Cin)
                v = w[((co0 + co) * Cin + gci) * 16 + tap];
            s_w[co][ci][tap] = v;
        }
        __syncthreads();

#pragma unroll 1
        for (int ci = 0; ci < 8; ci++) {
#pragma unroll
            for (int kh = 0; kh < 4; kh++) {
#pragma unroll
                for (int kw = 0; kw < 4; kw++) {
                    float a0 = s_in[ci][2 * oy0 + kh][2 * ox + kw];
                    float a1 = s_in[ci][2 * oy0 + 8 + kh][2 * ox + kw];
#pragma unroll
                    for (int u = 0; u < 8; u++) {
                        float wv = s_w[cg * 8 + u][ci][kh * 4 + kw];
                        acc0[u] += wv * a0;
                        acc1[u] += wv * a1;
                    }
                }
            }
        }
        __syncthreads();
    }

#pragma unroll
    for (int u = 0; u < 8; u++) {
        int co = co0 + cg * 8 + u;
        float b = bias[co];
        float v0 = acc0[u] + b;
        float v1 = acc1[u] + b;
        if (relu) { v0 = fmaxf(v0, 0.f); v1 = fmaxf(v1, 0.f); }
        int base = (n * Cout + co) * Ho;
        out[(base + oh0 + oy0) * Wo + ow0 + ox]     = v0;
        out[(base + oh0 + oy0 + 4) * Wo + ow0 + ox] = v1;
    }
}

// ---------------- convT k4 s2 p1 (+bias, optional relu), channel-concat input ----------------
// w layout: [Cin, Cout, 4, 4]. out[n,co,oh,ow] = b + sum_ci sum_{kh=(oh+1)%2 +2t} in[(oh+1-kh)/2] * w
// output tile 16x16, COUT tile 16; 256 threads: cg=tid>>7, sp=tid&127 -> (oy0, oy0+8).
__global__ __launch_bounds__(256)
void convT_k4s2_kernel(const float* __restrict__ inA, const float* __restrict__ inB, int Csplit,
                       const float* __restrict__ w, const float* __restrict__ bias,
                       float* __restrict__ out,
                       int N, int Cin, int Cout, int Hi, int Wi, int Ho, int Wo, int relu)
{
    __shared__ float s_in[8][10][11];
    __shared__ float s_w[16][8][16];

    int tid = threadIdx.x;
    int cg  = tid >> 7;   // 0..1
    int sp  = tid & 127;
    int oy0 = sp >> 4;    // 0..7
    int ox  = sp & 15;

    int nCo = (Cout + 15) >> 4;
    int n   = blockIdx.z / nCo;
    int co0 = (blockIdx.z % nCo) << 4;
    int oh0 = blockIdx.y * 16;
    int ow0 = blockIdx.x * 16;
    int ih0 = (oh0 >> 1) - 1;
    int iw0 = (ow0 >> 1) - 1;

    int oh_a = oh0 + oy0;       // second position: oh_a + 8 (same parity)
    int ow_g = ow0 + ox;
    int kh_base = (oh_a + 1) & 1;
    int kw_base = (ow_g + 1) & 1;
    // smem row/col indices for tap (kh_base, kw_base); tap+2 shifts index by -1
    int ra0 = (oh_a + 1 - kh_base) / 2 - ih0;   // in [1..5]
    int cc0 = (ow_g + 1 - kw_base) / 2 - iw0;

    int Cb = Cin - Csplit;

    float acc0[8], acc1[8];
#pragma unroll
    for (int u = 0; u < 8; u++) { acc0[u] = 0.f; acc1[u] = 0.f; }

    for (int ci0 = 0; ci0 < Cin; ci0 += 8) {
        for (int e = tid; e < 8 * 10 * 11; e += 256) {
            int ci = e / 110;
            int r  = (e / 11) % 10;
            int c  = e % 11;
            float v = 0.f;
            int gr = ih0 + r, gc = iw0 + c;
            if (c < 10 && gr >= 0 && gr < Hi && gc >= 0 && gc < Wi) {
                int gci = ci0 + ci;
                if (gci < Csplit)
                    v = inA[((n * Csplit + gci) * Hi + gr) * Wi + gc];
                else
                    v = inB[((n * Cb + (gci - Csplit)) * Hi + gr) * Wi + gc];
            }
            s_in[ci][r][c] = v;
        }
        for (int e = tid; e < 16 * 8 * 16; e += 256) {
            int co  = e >> 7;
            int ci  = (e >> 4) & 7;
            int tap = e & 15;
            float v = 0.f;
            if (co0 + co < Cout)
                v = w[((ci0 + ci) * Cout + co0 + co) * 16 + tap];
            s_w[co][ci][tap] = v;
        }
        __syncthreads();

#pragma unroll 1
        for (int ci = 0; ci < 8; ci++) {
#pragma unroll
            for (int dh = 0; dh < 2; dh++) {
#pragma unroll
                for (int dw = 0; dw < 2; dw++) {
                    int kh = kh_base + 2 * dh;
                    int kw = kw_base + 2 * dw;
                    int ra = ra0 - dh;
                    int cc = cc0 - dw;
                    float a0 = s_in[ci][ra][cc];
                    float a1 = s_in[ci][ra + 4][cc];
#pragma unroll
                    for (int u = 0; u < 8; u++) {
                        float wv = s_w[cg * 8 + u][ci][kh * 4 + kw];
                        acc0[u] += wv * a0;
                        acc1[u] += wv * a1;
                    }
                }
            }
        }
        __syncthreads();
    }

#pragma unroll
    for (int u = 0; u < 8; u++) {
        int co = co0 + cg * 8 + u;
        if (co < Cout) {
            float b = bias[co];
            float v0 = acc0[u] + b;
            float v1 = acc1[u] + b;
            if (relu) { v0 = fmaxf(v0, 0.f); v1 = fmaxf(v1, 0.f); }
            int base = (n * Cout + co) * Ho;
            out[(base + oh_a) * Wo + ow_g]       = v0;
            out[(base + oh_a + 8) * Wo + ow_g]   = v1;
        }
    }
}

// ---------------- 1x1 conv (channel-concat input) -> pixel-major z [P, 64] ----------------
// Block: 32 pixels x 64 outputs. 256 threads: d=tid&63, ps=tid>>6, pixels ps*8+i (i<8).
__global__ __launch_bounds__(256)
void conv1x1_kernel(const float* __restrict__ inA, const float* __restrict__ inB, int Csplit,
                    const float* __restrict__ w, const float* __restrict__ bias,
                    float* __restrict__ z, int Cin, int HW)
{
    __shared__ float s_w[64][64];   // [ci_local][d]
    __shared__ float s_x[64][32];   // [ci_local][pixel_local]

    int tid = threadIdx.x;
    int d   = tid & 63;
    int ps  = tid >> 6;  // 0..3
    int pbase = blockIdx.x * 32;
    int n  = pbase / HW;
    int hw = pbase - n * HW;
    int Cb = Cin - Csplit;

    float acc[8];
#pragma unroll
    for (int i = 0; i < 8; i++) acc[i] = 0.f;

    for (int c0 = 0; c0 < Cin; c0 += 64) {
        for (int e = tid; e < 64 * 64; e += 256) {
            int ci = e >> 6, dd = e & 63;
            s_w[ci][dd] = w[dd * Cin + c0 + ci];
        }
        for (int e = tid; e < 64 * 32; e += 256) {
            int ci = e >> 5, pl = e & 31;
            int gc = c0 + ci;
            float v;
            if (gc < Csplit)
                v = inA[(n * Csplit + gc) * HW + hw + pl];
            else
                v = inB[(n * Cb + (gc - Csplit)) * HW + hw + pl];
            s_x[ci][pl] = v;
        }
        __syncthreads();

#pragma unroll 4
        for (int ci = 0; ci < 64; ci++) {
            float wv = s_w[ci][d];
#pragma unroll
            for (int i = 0; i < 8; i++)
                acc[i] += wv * s_x[ci][ps * 8 + i];
        }
        __syncthreads();
    }

    float b = bias[d];
#pragma unroll
    for (int i = 0; i < 8; i++)
        z[(pbase + ps * 8 + i) * 64 + d] = acc[i] + b;
}

// ---------------- VQ: argmin_k ||z - e_k||^2 ; outputs idx, id(float), sum of min dists ----------------
// Block: 32 pixels, all 512 codes in chunks of 64. 256 threads: tx=tid&15 (4 codes), ty=tid>>4 (pixels ty, ty+16).
__global__ __launch_bounds__(256)
void quantize_kernel(const float* __restrict__ z, const float* __restrict__ embed,
                     const float* __restrict__ norms, int K,
                     int* __restrict__ idx_out, float* __restrict__ id_out, float* __restrict__ dsum)
{
    __shared__ float s_z[32][64];
    __shared__ float s_e[64][64];
    __shared__ float s_n[64];
    __shared__ float s_zn[32];

    int tid = threadIdx.x;
    int pbase = blockIdx.x * 32;

    for (int e = tid; e < 32 * 64; e += 256)
        s_z[e >> 6][e & 63] = z[(pbase + (e >> 6)) * 64 + (e & 63)];
    __syncthreads();
    if (tid < 32) {
        float s = 0.f;
        for (int d = 0; d < 64; d++) { float v = s_z[tid][d]; s += v * v; }
        s_zn[tid] = s;
    }

    int tx = tid & 15, ty = tid >> 4;
    float best0 = 3.4e38f, best1 = 3.4e38f;
    int bi0 = 0, bi1 = 0;

    for (int k0 = 0; k0 < K; k0 += 64) {
        for (int e = tid; e < 64 * 64; e += 256) {
            int dd = e >> 6, kl = e & 63;
            s_e[dd][kl] = embed[dd * K + k0 + kl];
        }
        if (tid < 64) s_n[tid] = norms[k0 + tid];
        __syncthreads();

        float acc0[4] = {0.f, 0.f, 0.f, 0.f};
        float acc1[4] = {0.f, 0.f, 0.f, 0.f};
#pragma unroll 4
        for (int d = 0; d < 64; d++) {
            float z0 = s_z[ty][d], z1 = s_z[ty + 16][d];
#pragma unroll
            for (int c = 0; c < 4; c++) {
                float ev = s_e[d][tx * 4 + c];
                acc0[c] += z0 * ev;
                acc1[c] += z1 * ev;
            }
        }
#pragma unroll
        for (int c = 0; c < 4; c++) {
            int k = k0 + tx * 4 + c;
            float d0 = s_n[tx * 4 + c] - 2.f * acc0[c];
            float d1 = s_n[tx * 4 + c] - 2.f * acc1[c];
            if (d0 < best0) { best0 = d0; bi0 = k; }
            if (d1 < best1) { best1 = d1; bi1 = k; }
        }
        __syncthreads();
    }

    // reduce over the 16 tx-lanes (segments of 16 within a warp)
#pragma unroll
    for (int off = 8; off > 0; off >>= 1) {
        float v0 = __shfl_down_sync(0xffffffffu, best0, off, 16);
        int   j0 = __shfl_down_sync(0xffffffffu, bi0,  off, 16);
        if (v0 < best0 || (v0 == best0 && j0 < bi0)) { best0 = v0; bi0 = j0; }
        float v1 = __shfl_down_sync(0xffffffffu, best1, off, 16);
        int   j1 = __shfl_down_sync(0xffffffffu, bi1,  off, 16);
        if (v1 < best1 || (v1 == best1 && j1 < bi1)) { best1 = v1; bi1 = j1; }
    }

    if (tx == 0) {
        int p0 = pbase + ty, p1 = pbase + ty + 16;
        idx_out[p0] = bi0;  idx_out[p1] = bi1;
        id_out[p0] = (float)bi0;  id_out[p1] = (float)bi1;
        float md = (best0 + s_zn[ty]) + (best1 + s_zn[ty + 16]);
        atomicAdd(dsum, md);
    }
}

// ---------------- scatter: quant[n,d,h,w] = embed[d, idx[n,h,w]] ----------------
__global__ void scatter_quant_kernel(const float* __restrict__ embed, const int* __restrict__ idx,
                                     float* __restrict__ out, int HW, int K, int total)
{
    int i = blockIdx.x * blockDim.x + threadIdx.x;
    if (i >= total) return;
    int hw = i % HW;
    int d  = (i / HW) & 63;
    int n  = i / (HW * 64);
    out[i] = embed[d * K + idx[n * HW + hw]];
}

// ---------------- finalize loss ----------------
__global__ void finalize_loss_kernel(float* __restrict__ out_loss)
{
    out_loss[0] = g_dsum[0] * (1.f / (16384.f * 64.f)) + g_dsum[1] * (1.f / (65536.f * 64.f));
}

// ---------------- launch ----------------
extern "C" void kernel_launch(void* const* d_in, const int* in_sizes, int n_in,
                              void* d_out, int out_size)
{
    const float* x       = (const float*)d_in[0];
    const float* wb1     = (const float*)d_in[1];
    const float* bb1     = (const float*)d_in[2];
    const float* wb2     = (const float*)d_in[3];
    const float* bb2     = (const float*)d_in[4];
    const float* wt1     = (const float*)d_in[5];
    const float* bt1     = (const float*)d_in[6];
    const float* wqt     = (const float*)d_in[7];
    const float* bqt     = (const float*)d_in[8];
    const float* embed_t = (const float*)d_in[9];
    const float* wdt     = (const float*)d_in[10];
    const float* bdt     = (const float*)d_in[11];
    const float* wqb     = (const float*)d_in[12];
    const float* bqb     = (const float*)d_in[13];
    const float* embed_b = (const float*)d_in[14];
    const float* wup     = (const float*)d_in[15];
    const float* bup     = (const float*)d_in[16];
    const float* wd1     = (const float*)d_in[17];
    const float* bd1     = (const float*)d_in[18];
    const float* wd2     = (const float*)d_in[19];
    const float* bd2     = (const float*)d_in[20];

    float* out = (float*)d_out;

    // output layout (flattened concat of reference returns)
    const int OFF_XHAT = 0;           // 16*3*256*256   = 3145728
    const int OFF_QT   = 3145728;     // 16*64*32*32    = 1048576
    const int OFF_QB   = 4194304;     // 16*64*64*64    = 4194304
    const int OFF_LOSS = 8388608;     // 1
    const int OFF_IDT  = 8388609;     // 16*32*32       = 16384
    const int OFF_IDB  = 8404993;     // 16*64*64       = 65536

    float *enc_b1, *enc_b, *enc_t, *zt, *zb, *dec_t, *up_t, *h;
    int *idx_t, *idx_b;
    float *norm_t, *norm_b, *dsum;
    cudaGetSymbolAddress((void**)&enc_b1, g_enc_b1);
    cudaGetSymbolAddress((void**)&enc_b,  g_enc_b);
    cudaGetSymbolAddress((void**)&enc_t,  g_enc_t);
    cudaGetSymbolAddress((void**)&zt,     g_zt);
    cudaGetSymbolAddress((void**)&zb,     g_zb);
    cudaGetSymbolAddress((void**)&dec_t,  g_dec_t);
    cudaGetSymbolAddress((void**)&up_t,   g_up_t);
    cudaGetSymbolAddress((void**)&h,      g_h);
    cudaGetSymbolAddress((void**)&idx_t,  g_idx_t);
    cudaGetSymbolAddress((void**)&idx_b,  g_idx_b);
    cudaGetSymbolAddress((void**)&norm_t, g_norm_t);
    cudaGetSymbolAddress((void**)&norm_b, g_norm_b);
    cudaGetSymbolAddress((void**)&dsum,   g_dsum);

    zero_sums_kernel<<<1, 1>>>();
    embed_norms_kernel<<<2, 256>>>(embed_t, norm_t, 512);
    embed_norms_kernel<<<2, 256>>>(embed_b, norm_b, 512);

    // encoder
    conv_s2k4_kernel<<<dim3(8, 16, 16 * 4), 256>>>(x, wb1, bb1, enc_b1,
        16, 3, 128, 256, 256, 128, 128, 1);
    conv_s2k4_kernel<<<dim3(4, 8, 16 * 4), 256>>>(enc_b1, wb2, bb2, enc_b,
        16, 128, 128, 128, 128, 64, 64, 1);
    conv_s2k4_kernel<<<dim3(2, 4, 16 * 4), 256>>>(enc_b, wt1, bt1, enc_t,
        16, 128, 128, 64, 64, 32, 32, 1);

    // top VQ
    conv1x1_kernel<<<16384 / 32, 256>>>(enc_t, enc_t, 128, wqt, bqt, zt, 128, 1024);
    quantize_kernel<<<16384 / 32, 256>>>(zt, embed_t, norm_t, 512, idx_t, out + OFF_IDT, dsum + 0);
    scatter_quant_kernel<<<(16 * 64 * 32 * 32) / 256, 256>>>(embed_t, idx_t, out + OFF_QT,
        1024, 512, 16 * 64 * 32 * 32);

    // decode top -> bottom VQ
    convT_k4s2_kernel<<<dim3(4, 4, 16 * 4), 256>>>(out + OFF_QT, out + OFF_QT, 64, wdt, bdt, dec_t,
        16, 64, 64, 32, 32, 64, 64, 0);
    conv1x1_kernel<<<65536 / 32, 256>>>(dec_t, enc_b, 64, wqb, bqb, zb, 192, 4096);
    quantize_kernel<<<65536 / 32, 256>>>(zb, embed_b, norm_b, 512, idx_b, out + OFF_IDB, dsum + 1);
    scatter_quant_kernel<<<(16 * 64 * 64 * 64) / 256, 256>>>(embed_b, idx_b, out + OFF_QB,
        4096, 512, 16 * 64 * 64 * 64);

    // decoder
    convT_k4s2_kernel<<<dim3(4, 4, 16 * 4), 256>>>(out + OFF_QT, out + OFF_QT, 64, wup, bup, up_t,
        16, 64, 64, 32, 32, 64, 64, 0);
    convT_k4s2_kernel<<<dim3(8, 8, 16 * 4), 256>>>(up_t, out + OFF_QB, 64, wd1, bd1, h,
        16, 128, 64, 64, 64, 128, 128, 1);
    convT_k4s2_kernel<<<dim3(16, 16, 16 * 1), 256>>>(h, h, 64, wd2, bd2, out + OFF_XHAT,
        16, 64, 3, 128, 128, 256, 256, 0);

    finalize_loss_kernel<<<1, 1>>>(out + OFF_LOSS);

    (void)in_sizes; (void)n_in; (void)out_size;
}